// round 7
// baseline (speedup 1.0000x reference)
#include <cuda_runtime.h>

#define THREADS 256
#define NWARP   (THREADS / 32)
#define NSUM    11
#define SLOT    12          // padded per-warp scratch stride (floats)
#define BATCH   8
#define MAXB    4096

// Per-row, per-warp fp32 partial sums (frozen numerics: exact round-2 values).
__device__ float g_scratch[MAXB * NWARP * SLOT];

__device__ __forceinline__ float ex2_approx(float t) {
    float r; asm("ex2.approx.f32 %0, %1;" : "=f"(r) : "f"(t)); return r;
}
__device__ __forceinline__ float rcp_approx(float t) {
    float r; asm("rcp.approx.f32 %0, %1;" : "=f"(r) : "f"(t)); return r;
}

// Branchless DP reciprocal: fp32 rcp seed + 2 Newton steps (DFMA only).
// Rel err < 1 ulp DP for normal inputs — indistinguishable after fp32 cast.
__device__ __forceinline__ double drcp(double d) {
    double r = (double)rcp_approx((float)d);
    double e = fma(-d, r, 1.0);
    r = fma(r, e, r);
    e = fma(-d, r, 1.0);
    r = fma(r, e, r);
    return r;
}

// ===== EXACT round-2 element body: do not reorder, fp32 numerics frozen =====
//  0: s        1: s^2
//  2: sp       3: sp*x      4: sp*x^2
//  5: s*sp     6: s*sp*x    7: s*sp*x^2
//  8: s^2*sp   9: s^2*sp*x 10: s^2*sp*x^2
#define ELEM_BODY(xv)                                               \
    do {                                                            \
        float _x   = (xv);                                          \
        float _t   = fmaf(c1, _x, c2);      /* -u*log2e */          \
        float _e   = ex2_approx(_t);        /* exp(-u)  */          \
        float _s   = rcp_approx(1.0f + _e); /* sigmoid  */          \
        float _sp  = fmaf(-_s, _s, _s);     /* s(1-s)   */          \
        float _ssp = _s * _sp;                                      \
        float _s2sp= _s * _ssp;                                     \
        float _x2  = _x * _x;                                       \
        acc0  += _s;                                                \
        acc1   = fmaf(_s, _s, acc1);                                \
        acc2  += _sp;                                               \
        acc3   = fmaf(_sp, _x, acc3);                               \
        acc4   = fmaf(_sp, _x2, acc4);                              \
        acc5  += _ssp;                                              \
        acc6   = fmaf(_ssp, _x, acc6);                              \
        acc7   = fmaf(_ssp, _x2, acc7);                             \
        acc8  += _s2sp;                                             \
        acc9   = fmaf(_s2sp, _x, acc9);                             \
        acc10  = fmaf(_s2sp, _x2, acc10);                           \
    } while (0)

__global__ __launch_bounds__(THREADS) void nsab_reduce_kernel(
    const float* __restrict__ x, const float* __restrict__ a,
    const float* __restrict__ b, int N)
{
    const int row = blockIdx.x;
    const int tid = threadIdx.x;

    const float* xrow = x + (size_t)row * (size_t)N;
    const float LOG2E = 1.4426950408889634f;
    const float c1 = -__ldg(a + row) * LOG2E;
    const float c2 = -__ldg(b + row) * LOG2E;

    float acc0 = 0.f, acc1 = 0.f, acc2 = 0.f, acc3 = 0.f, acc4 = 0.f,
          acc5 = 0.f, acc6 = 0.f, acc7 = 0.f, acc8 = 0.f, acc9 = 0.f,
          acc10 = 0.f;

    const int n4 = N >> 2;
    const float4* __restrict__ x4 = (const float4*)xrow;

    // Main loop: BATCH front-issued float4 loads; per-thread element order is
    // identical to the non-batched strided loop (numerics frozen).
    int i = tid;
    for (; i + (BATCH - 1) * THREADS < n4; i += BATCH * THREADS) {
        float4 v[BATCH];
#pragma unroll
        for (int j = 0; j < BATCH; ++j) v[j] = x4[i + j * THREADS];
#pragma unroll
        for (int j = 0; j < BATCH; ++j) {
            ELEM_BODY(v[j].x);
            ELEM_BODY(v[j].y);
            ELEM_BODY(v[j].z);
            ELEM_BODY(v[j].w);
        }
    }
    // Remainder float4s (unused for N=8192).
    for (; i < n4; i += THREADS) {
        float4 v = x4[i];
        ELEM_BODY(v.x);
        ELEM_BODY(v.y);
        ELEM_BODY(v.z);
        ELEM_BODY(v.w);
    }
    // Scalar tail (N % 4 != 0; unused for N=8192).
    for (int k = (n4 << 2) + tid; k < N; k += THREADS) {
        ELEM_BODY(xrow[k]);
    }

    float sums[NSUM] = {acc0, acc1, acc2, acc3, acc4, acc5,
                        acc6, acc7, acc8, acc9, acc10};

    // fp32 warp tree reduce — frozen.
#pragma unroll
    for (int k = 0; k < NSUM; ++k) {
#pragma unroll
        for (int o = 16; o > 0; o >>= 1)
            sums[k] += __shfl_xor_sync(0xffffffffu, sums[k], o);
    }

    // Lane 0 of each warp writes its 11 fp32 partials; no barrier, no smem.
    const int wid  = tid >> 5;
    const int lane = tid & 31;
    if (lane == 0) {
        float* dst = g_scratch + ((size_t)row * NWARP + wid) * SLOT;
#pragma unroll
        for (int k = 0; k < NSUM; ++k) dst[k] = sums[k];
    }
}

// One thread per row. DP domain may be freely restructured (perturbations
// ~1e-16, invisible after fp32 cast): pairwise fold + Newton-reciprocal
// division, fully branchless — short dependency chain, no divide subroutine.
__global__ __launch_bounds__(32) void nsab_solve_kernel(
    const float* __restrict__ mean, const float* __restrict__ var,
    float* __restrict__ out, int B, int N)
{
    const int row = blockIdx.x * 32 + threadIdx.x;
    if (row >= B) return;

    const float* src = g_scratch + (size_t)row * NWARP * SLOT;
    double S[NSUM];
#pragma unroll
    for (int k = 0; k < NSUM; ++k) {
        // Pairwise (depth-3) DP fold of 8 warp partials.
        double t01 = (double)src[0 * SLOT + k] + (double)src[1 * SLOT + k];
        double t23 = (double)src[2 * SLOT + k] + (double)src[3 * SLOT + k];
        double t45 = (double)src[4 * SLOT + k] + (double)src[5 * SLOT + k];
        double t67 = (double)src[6 * SLOT + k] + (double)src[7 * SLOT + k];
        S[k] = (t01 + t23) + (t45 + t67);
    }

    const double invN = 1.0 / (double)N;
    const double fm     = S[0]  * invN;   // m(f)
    const double ms2    = S[1]  * invN;   // m(f^2)
    const double msp0   = S[2]  * invN;   // m(sp)
    const double msp1   = S[3]  * invN;   // m(sp x)
    const double msp2   = S[4]  * invN;   // m(sp x^2)
    const double mssp0  = S[5]  * invN;   // m(s sp)
    const double mssp1  = S[6]  * invN;   // m(s sp x)
    const double mssp2  = S[7]  * invN;   // m(s sp x^2)
    const double ms2sp0 = S[8]  * invN;   // m(s^2 sp)
    const double ms2sp1 = S[9]  * invN;   // m(s^2 sp x)
    const double ms2sp2 = S[10] * invN;   // m(s^2 sp x^2)

    const double dem_db   = msp0;
    const double dem_da   = msp1;
    const double d2em_db2 = msp0 - 2.0 * mssp0;   // m(spp)
    const double d2em_dab = msp1 - 2.0 * mssp1;   // m(spp x)
    const double d2em_da2 = msp2 - 2.0 * mssp2;   // m(spp x^2)
    const double mg   = 2.0 * mssp0 - 3.0 * ms2sp0;  // m(sp^2 + f spp)
    const double mgx  = 2.0 * mssp1 - 3.0 * ms2sp1;
    const double mgx2 = 2.0 * mssp2 - 3.0 * ms2sp2;

    const double em = fm - (double)__ldg(mean + row);
    const double ev = ms2 - fm * fm - (double)__ldg(var + row);

    const double dev_da   = 2.0 * (mssp1 - fm * dem_da);
    const double dev_db   = 2.0 * (mssp0 - fm * dem_db);
    const double d2ev_da2 = 2.0 * (mgx2 - dem_da * dem_da - fm * d2em_da2);
    const double d2ev_dab = 2.0 * (mgx  - dem_da * dem_db - fm * d2em_dab);
    const double d2ev_db2 = 2.0 * (mg   - dem_db * dem_db - fm * d2em_db2);

    const double dl_da = 2.0 * (em * dem_da + ev * dev_da);
    const double dl_db = 2.0 * (em * dem_db + ev * dev_db);

    const double d2l_da2 = 2.0 * (dem_da * dem_da + em * d2em_da2 +
                                  dev_da * dev_da + ev * d2ev_da2);
    const double d2l_dab = 2.0 * (dem_da * dem_db + em * d2em_dab +
                                  dev_da * dev_db + ev * d2ev_dab);
    const double d2l_db2 = 2.0 * (dem_db * dem_db + em * d2em_db2 +
                                  dev_db * dev_db + ev * d2ev_db2);

    const double den = d2l_da2 * d2l_db2 - d2l_dab * d2l_dab;
    const double inv = drcp(den);
    const double na  = (dl_da * d2l_db2 - dl_db * d2l_dab) * inv;
    const double nb  = (dl_db * d2l_da2 - dl_da * d2l_dab) * inv;

    out[row]     = (float)na;
    out[row + B] = (float)nb;
}

extern "C" void kernel_launch(void* const* d_in, const int* in_sizes, int n_in,
                              void* d_out, int out_size)
{
    const float* x    = (const float*)d_in[0];
    const float* a    = (const float*)d_in[1];
    const float* b    = (const float*)d_in[2];
    const float* mean = (const float*)d_in[3];
    const float* var  = (const float*)d_in[4];
    // d_in[5] = dim (always 1) — ignored.

    const int B = in_sizes[1];
    const int N = in_sizes[0] / B;

    nsab_reduce_kernel<<<B, THREADS>>>(x, a, b, N);
    nsab_solve_kernel<<<(B + 31) / 32, 32>>>(mean, var, (float*)d_out, B, N);
}

// round 8
// speedup vs baseline: 1.2323x; 1.2323x over previous
#include <cuda_runtime.h>

#define THREADS 256
#define NWARP   (THREADS / 32)
#define NSUM    11
#define SLOT    12          // padded per-row scratch stride (doubles)
#define BATCH   8
#define MAXB    4096

// Per-row folded DP sums (11 used, padded to 12).
__device__ double g_dscratch[MAXB * SLOT];

__device__ __forceinline__ float ex2_approx(float t) {
    float r; asm("ex2.approx.f32 %0, %1;" : "=f"(r) : "f"(t)); return r;
}
__device__ __forceinline__ float rcp_approx(float t) {
    float r; asm("rcp.approx.f32 %0, %1;" : "=f"(r) : "f"(t)); return r;
}

// Branchless DP reciprocal: fp32 rcp seed + 2 Newton steps (DFMA only).
__device__ __forceinline__ double drcp(double d) {
    double r = (double)rcp_approx((float)d);
    double e = fma(-d, r, 1.0);
    r = fma(r, e, r);
    e = fma(-d, r, 1.0);
    r = fma(r, e, r);
    return r;
}

// ===== EXACT round-2 element body: do not reorder, fp32 numerics frozen =====
//  0: s        1: s^2
//  2: sp       3: sp*x      4: sp*x^2
//  5: s*sp     6: s*sp*x    7: s*sp*x^2
//  8: s^2*sp   9: s^2*sp*x 10: s^2*sp*x^2
#define ELEM_BODY(xv)                                               \
    do {                                                            \
        float _x   = (xv);                                          \
        float _t   = fmaf(c1, _x, c2);      /* -u*log2e */          \
        float _e   = ex2_approx(_t);        /* exp(-u)  */          \
        float _s   = rcp_approx(1.0f + _e); /* sigmoid  */          \
        float _sp  = fmaf(-_s, _s, _s);     /* s(1-s)   */          \
        float _ssp = _s * _sp;                                      \
        float _s2sp= _s * _ssp;                                     \
        float _x2  = _x * _x;                                       \
        acc0  += _s;                                                \
        acc1   = fmaf(_s, _s, acc1);                                \
        acc2  += _sp;                                               \
        acc3   = fmaf(_sp, _x, acc3);                               \
        acc4   = fmaf(_sp, _x2, acc4);                              \
        acc5  += _ssp;                                              \
        acc6   = fmaf(_ssp, _x, acc6);                              \
        acc7   = fmaf(_ssp, _x2, acc7);                             \
        acc8  += _s2sp;                                             \
        acc9   = fmaf(_s2sp, _x, acc9);                             \
        acc10  = fmaf(_s2sp, _x2, acc10);                           \
    } while (0)

__global__ __launch_bounds__(THREADS) void nsab_reduce_kernel(
    const float* __restrict__ x, const float* __restrict__ a,
    const float* __restrict__ b, int N)
{
    const int row = blockIdx.x;
    const int tid = threadIdx.x;

    const float* xrow = x + (size_t)row * (size_t)N;
    const float LOG2E = 1.4426950408889634f;
    const float c1 = -__ldg(a + row) * LOG2E;
    const float c2 = -__ldg(b + row) * LOG2E;

    float acc0 = 0.f, acc1 = 0.f, acc2 = 0.f, acc3 = 0.f, acc4 = 0.f,
          acc5 = 0.f, acc6 = 0.f, acc7 = 0.f, acc8 = 0.f, acc9 = 0.f,
          acc10 = 0.f;

    const int n4 = N >> 2;
    const float4* __restrict__ x4 = (const float4*)xrow;

    // Main loop: BATCH front-issued float4 loads; per-thread element order is
    // identical to the non-batched strided loop (numerics frozen).
    int i = tid;
    for (; i + (BATCH - 1) * THREADS < n4; i += BATCH * THREADS) {
        float4 v[BATCH];
#pragma unroll
        for (int j = 0; j < BATCH; ++j) v[j] = x4[i + j * THREADS];
#pragma unroll
        for (int j = 0; j < BATCH; ++j) {
            ELEM_BODY(v[j].x);
            ELEM_BODY(v[j].y);
            ELEM_BODY(v[j].z);
            ELEM_BODY(v[j].w);
        }
    }
    // Remainder float4s (unused for N=8192).
    for (; i < n4; i += THREADS) {
        float4 v = x4[i];
        ELEM_BODY(v.x);
        ELEM_BODY(v.y);
        ELEM_BODY(v.z);
        ELEM_BODY(v.w);
    }
    // Scalar tail (N % 4 != 0; unused for N=8192).
    for (int k = (n4 << 2) + tid; k < N; k += THREADS) {
        ELEM_BODY(xrow[k]);
    }

    float sums[NSUM] = {acc0, acc1, acc2, acc3, acc4, acc5,
                        acc6, acc7, acc8, acc9, acc10};

    // fp32 warp tree reduce — frozen.
#pragma unroll
    for (int k = 0; k < NSUM; ++k) {
#pragma unroll
        for (int o = 16; o > 0; o >>= 1)
            sums[k] += __shfl_xor_sync(0xffffffffu, sums[k], o);
    }

    // Warp leaders -> smem; threads 0..10 each fold one sum across the 8
    // warps in DP (identical pairwise order to round 7 — bit-safe) and write
    // one double per sum. DP cost here is tiny and hidden by other CTAs.
    __shared__ float red[NWARP][NSUM];
    const int wid  = tid >> 5;
    const int lane = tid & 31;
    if (lane == 0) {
#pragma unroll
        for (int k = 0; k < NSUM; ++k) red[wid][k] = sums[k];
    }
    __syncthreads();

    if (tid < NSUM) {
        const int k = tid;
        double t01 = (double)red[0][k] + (double)red[1][k];
        double t23 = (double)red[2][k] + (double)red[3][k];
        double t45 = (double)red[4][k] + (double)red[5][k];
        double t67 = (double)red[6][k] + (double)red[7][k];
        g_dscratch[(size_t)row * SLOT + k] = (t01 + t23) + (t45 + t67);
    }
}

// One thread per row: load 11 folded doubles + branchless DP epilogue
// (~90 FP64 instructions, no conversions, no divides).
__global__ __launch_bounds__(32) void nsab_solve_kernel(
    const float* __restrict__ mean, const float* __restrict__ var,
    float* __restrict__ out, int B, int N)
{
    const int row = blockIdx.x * 32 + threadIdx.x;
    if (row >= B) return;

    const double* __restrict__ src = g_dscratch + (size_t)row * SLOT;
    double S[NSUM];
#pragma unroll
    for (int k = 0; k < NSUM; ++k) S[k] = src[k];

    const double invN = 1.0 / (double)N;
    const double fm     = S[0]  * invN;   // m(f)
    const double ms2    = S[1]  * invN;   // m(f^2)
    const double msp0   = S[2]  * invN;   // m(sp)
    const double msp1   = S[3]  * invN;   // m(sp x)
    const double msp2   = S[4]  * invN;   // m(sp x^2)
    const double mssp0  = S[5]  * invN;   // m(s sp)
    const double mssp1  = S[6]  * invN;   // m(s sp x)
    const double mssp2  = S[7]  * invN;   // m(s sp x^2)
    const double ms2sp0 = S[8]  * invN;   // m(s^2 sp)
    const double ms2sp1 = S[9]  * invN;   // m(s^2 sp x)
    const double ms2sp2 = S[10] * invN;   // m(s^2 sp x^2)

    const double dem_db   = msp0;
    const double dem_da   = msp1;
    const double d2em_db2 = msp0 - 2.0 * mssp0;   // m(spp)
    const double d2em_dab = msp1 - 2.0 * mssp1;   // m(spp x)
    const double d2em_da2 = msp2 - 2.0 * mssp2;   // m(spp x^2)
    const double mg   = 2.0 * mssp0 - 3.0 * ms2sp0;  // m(sp^2 + f spp)
    const double mgx  = 2.0 * mssp1 - 3.0 * ms2sp1;
    const double mgx2 = 2.0 * mssp2 - 3.0 * ms2sp2;

    const double em = fm - (double)__ldg(mean + row);
    const double ev = ms2 - fm * fm - (double)__ldg(var + row);

    const double dev_da   = 2.0 * (mssp1 - fm * dem_da);
    const double dev_db   = 2.0 * (mssp0 - fm * dem_db);
    const double d2ev_da2 = 2.0 * (mgx2 - dem_da * dem_da - fm * d2em_da2);
    const double d2ev_dab = 2.0 * (mgx  - dem_da * dem_db - fm * d2em_dab);
    const double d2ev_db2 = 2.0 * (mg   - dem_db * dem_db - fm * d2em_db2);

    const double dl_da = 2.0 * (em * dem_da + ev * dev_da);
    const double dl_db = 2.0 * (em * dem_db + ev * dev_db);

    const double d2l_da2 = 2.0 * (dem_da * dem_da + em * d2em_da2 +
                                  dev_da * dev_da + ev * d2ev_da2);
    const double d2l_dab = 2.0 * (dem_da * dem_db + em * d2em_dab +
                                  dev_da * dev_db + ev * d2ev_dab);
    const double d2l_db2 = 2.0 * (dem_db * dem_db + em * d2em_db2 +
                                  dev_db * dev_db + ev * d2ev_db2);

    const double den = d2l_da2 * d2l_db2 - d2l_dab * d2l_dab;
    const double inv = drcp(den);
    const double na  = (dl_da * d2l_db2 - dl_db * d2l_dab) * inv;
    const double nb  = (dl_db * d2l_da2 - dl_da * d2l_dab) * inv;

    out[row]     = (float)na;
    out[row + B] = (float)nb;
}

extern "C" void kernel_launch(void* const* d_in, const int* in_sizes, int n_in,
                              void* d_out, int out_size)
{
    const float* x    = (const float*)d_in[0];
    const float* a    = (const float*)d_in[1];
    const float* b    = (const float*)d_in[2];
    const float* mean = (const float*)d_in[3];
    const float* var  = (const float*)d_in[4];
    // d_in[5] = dim (always 1) — ignored.

    const int B = in_sizes[1];
    const int N = in_sizes[0] / B;

    nsab_reduce_kernel<<<B, THREADS>>>(x, a, b, N);
    nsab_solve_kernel<<<(B + 31) / 32, 32>>>(mean, var, (float*)d_out, B, N);
}